// round 2
// baseline (speedup 1.0000x reference)
#include <cuda_runtime.h>
#include <math.h>
#include <stdint.h>

#define B 8
#define UP 8
#define A 32
#define L 3264
#define H 256
#define BSZ 12
#define KCS 12
#define ND 61
#define NPT (UP*ND)        /* 488 */
#define L4 (L/4)           /* 816 */
#define NM (B*UP)          /* 64 */
#define M2L (2*L)          /* 6528 */
#define NOUT 576
#define KSPLIT 4
#define KLEN (L/KSPLIT)    /* 816 */
#define AG 4
#define NAG (A/AG)         /* 8 */
#define GK1 16
#define GKLEN (M2L/GK1)    /* 408 */

// ---------------- scratch (static device globals; no allocation) ----------------
__device__ float2 d_S[KSPLIT][B*A][NPT];      // ~4 MB partial DFT sums
__device__ int    d_toff[NM];
__device__ float  d_m[NM];
__device__ float2 d_phm[NM*L];                // 1.67 MB
__device__ float2 d_phT[NM*L];                // 1.67 MB
__device__ float2 d_havg[NM*A*L4];            // 13.4 MB
__device__ float2 d_res[B*A*L];               // 6.7 MB
__device__ float  d_energy[NM*A];
__device__ float  d_feat[NM*M2L];             // 1.67 MB
__device__ float  d_h1pre[GK1][NM][H];
__device__ float  d_h1[NM*H];
__device__ float  d_mlp[NM*NOUT];
__device__ float2 d_wm[NM*BSZ*BSZ];

// ---------------- K1: partial DFT at the 488 candidate delay bins ----------------
// grid (KSPLIT, NAG, B), block 512. Thread = one (up,d) point; 4 antennas per block.
__global__ void k_dft(const float* __restrict__ lr, const float* __restrict__ li,
                      const int* __restrict__ cs) {
    __shared__ float2 sls[AG][KLEN];   // 26112 B
    int ks = blockIdx.x, ag = blockIdx.y, b = blockIdx.z;
    int tid = threadIdx.x;
    int k0 = ks * KLEN;
    for (int e = tid; e < AG*KLEN; e += blockDim.x) {
        int ai = e / KLEN, kk = e - ai*KLEN;
        int off = (b*A + ag*AG + ai)*L + k0 + kk;
        sls[ai][kk] = make_float2(lr[off], li[off]);
    }
    __syncthreads();
    int p = tid;
    if (p >= NPT) return;
    int up = p / ND, dd = p - up*ND;
    int ip = ((KCS - cs[up]) % KCS) * (L / KCS);
    int n = (ip + dd - 30 + L) % L;

    const double w0 = 6.283185307179586476925286766559 / (double)L;
    float2 w;
    { float th = (float)(w0 * (double)n); sincosf(th, &w.y, &w.x); }

    float2 S0 = {0.f,0.f}, S1 = {0.f,0.f}, S2 = {0.f,0.f}, S3 = {0.f,0.f};
    for (int c = 0; c < KLEN; c += 272) {
        int r = (int)(((long long)(k0 + c) * (long long)n) % (long long)L);
        float2 z;
        { float th = (float)(w0 * (double)r); sincosf(th, &z.y, &z.x); }
        #pragma unroll 4
        for (int kk = c; kk < c + 272; kk++) {
            float2 v0 = sls[0][kk], v1 = sls[1][kk], v2 = sls[2][kk], v3 = sls[3][kk];
            S0.x += v0.x*z.x - v0.y*z.y;  S0.y += v0.x*z.y + v0.y*z.x;
            S1.x += v1.x*z.x - v1.y*z.y;  S1.y += v1.x*z.y + v1.y*z.x;
            S2.x += v2.x*z.x - v2.y*z.y;  S2.y += v2.x*z.y + v2.y*z.x;
            S3.x += v3.x*z.x - v3.y*z.y;  S3.y += v3.x*z.y + v3.y*z.x;
            float zr = z.x*w.x - z.y*w.y;
            float zi = z.x*w.y + z.y*w.x;
            z.x = zr; z.y = zi;
        }
    }
    int abase = b*A + ag*AG;
    d_S[ks][abase+0][p] = S0;
    d_S[ks][abase+1][p] = S1;
    d_S[ks][abase+2][p] = S2;
    d_S[ks][abase+3][p] = S3;
}

// ---------------- K2: power reduce over (ks, a) + argmax over d ----------------
__global__ void k_peak(const int* __restrict__ cs) {
    __shared__ float sp[ND];
    int up = blockIdx.x, b = blockIdx.y;
    int tid = threadIdx.x;
    if (tid < ND) {
        int pt = up*ND + tid;
        float s = 0.f;
        for (int a = 0; a < A; a++) {
            float2 t = {0.f, 0.f};
            #pragma unroll
            for (int ks = 0; ks < KSPLIT; ks++) {
                float2 v = d_S[ks][b*A + a][pt];
                t.x += v.x; t.y += v.y;
            }
            s += t.x*t.x + t.y*t.y;
        }
        sp[tid] = s;
    }
    __syncthreads();
    if (tid == 0) {
        float best = sp[0]; int bd = 0;
        for (int i = 1; i < ND; i++) if (sp[i] > best) { best = sp[i]; bd = i; }
        int toff = bd - 30;
        int ipk = ((KCS - cs[up]) % KCS) * (L / KCS);
        d_toff[b*UP + up] = toff;
        d_m[b*UP + up]    = (float)(toff + ipk);
    }
}

// accurate sin/cos of a (possibly huge) fp32 phase: double range reduction of the
// exact fp32 value — matches libdevice/XLA sin/cos regardless of fast-math flags.
__device__ __forceinline__ float2 expi_big(float th) {
    const double TWO_PI = 6.283185307179586476925286766559;
    const double INV_TWO_PI = 0.15915494309189533576888376337251;
    double x = (double)th;
    double r = x - TWO_PI * rint(x * INV_TWO_PI);
    float2 e; sincosf((float)r, &e.y, &e.x);
    return e;
}

// ---------------- K3: phasor tables (reproduce reference fp32 phase exactly) ----------------
__global__ void k_phasor() {
    int i = blockIdx.x * blockDim.x + threadIdx.x;   // exactly NM*L
    int bu = i / L, n = i - bu*L;
    const float W = (float)(6.283185307179586476925286766559 / (double)L);
    float nf = (float)n;
    float wm = W * d_m[bu];                 // fl(w*m)
    d_phm[i] = expi_big(wm * nf);           // fl(fl(w*m)*n)
    float wt = W * (float)d_toff[bu];
    d_phT[i] = expi_big(wt * nf);
}

// ---------------- K4: h_avg = mean over 4 of ls*phasor_m ----------------
__global__ void k_havg(const float* __restrict__ lr, const float* __restrict__ li) {
    int i = blockIdx.x * blockDim.x + threadIdx.x;   // exactly NM*A*L4
    int j = i % L4; int r = i / L4; int a = r % A; int bu = r / A; int b = bu / UP;
    int lsb = (b*A + a)*L + 4*j;
    int phb = bu*L + 4*j;
    float sx = 0.f, sy = 0.f;
    #pragma unroll
    for (int q = 0; q < 4; q++) {
        float xr = lr[lsb+q], xi = li[lsb+q];
        float2 ph = d_phm[phb+q];
        sx += xr*ph.x - xi*ph.y;
        sy += xr*ph.y + xi*ph.x;
    }
    d_havg[i] = make_float2(sx*0.25f, sy*0.25f);
}

// linear interp on the LOCC grid (matches jnp.interp incl. edge clamping)
__device__ __forceinline__ float2 hinterp(int bu, int a, int n) {
    const float2* row = &d_havg[(bu*A + a)*L4];
    if (n < 2)     return row[0];
    if (n > L-3)   return row[L4-1];
    float x = (float)n - 1.5f;
    int j = (int)(x * 0.25f);
    float t = (x - 4.0f*(float)j) * 0.25f;
    float2 v0 = row[j], v1 = row[j+1];
    return make_float2(v0.x + t*(v1.x - v0.x), v0.y + t*(v1.y - v0.y));
}

// ---------------- K5: residual = ls - sum_up h_interp*conj(phasor_m) ----------------
__global__ void k_residual(const float* __restrict__ lr, const float* __restrict__ li) {
    int i = blockIdx.x * blockDim.x + threadIdx.x;   // exactly B*A*L
    int n = i % L; int r = i / L; int a = r % A; int b = r / A;
    float ax = lr[i], ay = li[i];
    #pragma unroll
    for (int up = 0; up < UP; up++) {
        int bu = b*UP + up;
        float2 hi = hinterp(bu, a, n);
        float2 ph = d_phm[bu*L + n];
        ax -= hi.x*ph.x + hi.y*ph.y;     // hi * conj(ph)
        ay -= hi.y*ph.x - hi.x*ph.y;
    }
    d_res[i] = make_float2(ax, ay);
}

__device__ __forceinline__ float2 hres_val(int bu, int a, int n, int b) {
    float2 hi = hinterp(bu, a, n);
    float2 rs = d_res[(b*A + a)*L + n];
    float2 ph = d_phm[bu*L + n];
    return make_float2(hi.x + rs.x*ph.x - rs.y*ph.y,
                       hi.y + rs.x*ph.y + rs.y*ph.x);
}

// ---------------- K6: energies per (b,up,a) ----------------
__global__ void k_energy() {
    __shared__ float red[8];
    int bu = blockIdx.x / A, a = blockIdx.x % A, b = bu / UP;
    int t = threadIdx.x;
    float s = 0.f;
    for (int n = t; n < L; n += 256) {
        float2 h = hres_val(bu, a, n, b);
        s += h.x*h.x + h.y*h.y;
    }
    #pragma unroll
    for (int o = 16; o; o >>= 1) s += __shfl_down_sync(0xffffffffu, s, o);
    if ((t & 31) == 0) red[t >> 5] = s;
    __syncthreads();
    if (t == 0) {
        float tot = 0.f;
        #pragma unroll
        for (int wq = 0; wq < 8; wq++) tot += red[wq];
        d_energy[blockIdx.x] = tot;
    }
}

// ---------------- K7: argmax antenna + build MLP features ----------------
__global__ void k_feat() {
    __shared__ int s_ai;
    int bu = blockIdx.x, b = bu / UP;
    if (threadIdx.x == 0) {
        float best = d_energy[bu*A]; int bi = 0;
        for (int a = 1; a < A; a++) {
            float e = d_energy[bu*A + a];
            if (e > best) { best = e; bi = a; }
        }
        s_ai = bi;
    }
    __syncthreads();
    int a = s_ai;
    for (int n = threadIdx.x; n < L; n += blockDim.x) {
        float2 h = hres_val(bu, a, n, b);
        d_feat[bu*M2L + n]     = h.x;
        d_feat[bu*M2L + L + n] = h.y;
    }
}

// ---------------- K8a: GEMM1 split-K  (64x6528)@(6528x256) ----------------
__global__ void k_gemm1(const float* __restrict__ W1) {
    __shared__ float sA[64][8];
    __shared__ float sB[8][64];
    int ks = blockIdx.x, nt = blockIdx.y;
    int t = threadIdx.x;
    int tx = t & 15, ty = t >> 4;
    float acc[4][4] = {};
    int k0 = ks * GKLEN;
    for (int c = 0; c < GKLEN; c += 8) {
        {
            int e = t;       int m = e >> 3, kk = e & 7;
            sA[m][kk] = d_feat[m*M2L + k0 + c + kk];
            e = t + 256;     m = e >> 3;    kk = e & 7;
            sA[m][kk] = d_feat[m*M2L + k0 + c + kk];
        }
        {
            int e = t;       int kk = e >> 6, nn = e & 63;
            sB[kk][nn] = W1[(k0 + c + kk)*H + nt*64 + nn];
            e = t + 256;     kk = e >> 6;    nn = e & 63;
            sB[kk][nn] = W1[(k0 + c + kk)*H + nt*64 + nn];
        }
        __syncthreads();
        #pragma unroll
        for (int kk = 0; kk < 8; kk++) {
            float a0 = sA[ty*4+0][kk], a1 = sA[ty*4+1][kk];
            float a2 = sA[ty*4+2][kk], a3 = sA[ty*4+3][kk];
            float b0 = sB[kk][tx*4+0], b1 = sB[kk][tx*4+1];
            float b2 = sB[kk][tx*4+2], b3 = sB[kk][tx*4+3];
            acc[0][0] += a0*b0; acc[0][1] += a0*b1; acc[0][2] += a0*b2; acc[0][3] += a0*b3;
            acc[1][0] += a1*b0; acc[1][1] += a1*b1; acc[1][2] += a1*b2; acc[1][3] += a1*b3;
            acc[2][0] += a2*b0; acc[2][1] += a2*b1; acc[2][2] += a2*b2; acc[2][3] += a2*b3;
            acc[3][0] += a3*b0; acc[3][1] += a3*b1; acc[3][2] += a3*b2; acc[3][3] += a3*b3;
        }
        __syncthreads();
    }
    #pragma unroll
    for (int r = 0; r < 4; r++)
        #pragma unroll
        for (int cc = 0; cc < 4; cc++)
            d_h1pre[ks][ty*4+r][nt*64 + tx*4+cc] = acc[r][cc];
}

// ---------------- K8b: reduce split-K + bias + relu ----------------
__global__ void k_h1(const float* __restrict__ b1) {
    int m = blockIdx.x, t = threadIdx.x;
    float s = b1[t];
    #pragma unroll
    for (int ks = 0; ks < GK1; ks++) s += d_h1pre[ks][m][t];
    d_h1[m*H + t] = s > 0.f ? s : 0.f;
}

// ---------------- K8c: GEMM2 (64x256)@(256x576) + bias ----------------
__global__ void k_gemm2(const float* __restrict__ W2, const float* __restrict__ b2) {
    __shared__ float sh1[H];
    int m = blockIdx.x, t = threadIdx.x;
    if (t < H) sh1[t] = d_h1[m*H + t];
    __syncthreads();
    float s = b2[t];
    for (int k = 0; k < H; k++) s += sh1[k] * W2[k*NOUT + t];
    d_mlp[m*NOUT + t] = s;
}

// ---------------- K8d: Rm = A Aᴴ + I, invert (Gauss-Jordan), Wmmse = Cm inv(Rm) ----------------
__global__ void k_wmmse() {
    __shared__ float2 RM[12][24];
    __shared__ float2 sAr[144];
    __shared__ float2 sCm[144];
    __shared__ float2 fvec[12];
    int bu = blockIdx.x, t = threadIdx.x;   // 288 threads
    const float* o = &d_mlp[bu*NOUT];
    if (t < 144) {
        sCm[t] = make_float2(o[t],       o[144 + t]);
        sAr[t] = make_float2(o[288 + t], o[432 + t]);
    }
    __syncthreads();
    if (t < 144) {
        int i = t / 12, j = t % 12;
        float rr = (i == j) ? 1.f : 0.f, ri = 0.f;
        #pragma unroll
        for (int k = 0; k < 12; k++) {
            float2 ax = sAr[i*12 + k], bx = sAr[j*12 + k];
            rr += ax.x*bx.x + ax.y*bx.y;      // a * conj(b)
            ri += ax.y*bx.x - ax.x*bx.y;
        }
        RM[i][j]      = make_float2(rr, ri);
        RM[i][12 + j] = make_float2(i == j ? 1.f : 0.f, 0.f);
    }
    __syncthreads();
    int r = t / 24, c = t % 24;
    for (int p = 0; p < 12; p++) {
        if (t < 12) fvec[t] = RM[t][p];
        __syncthreads();
        if (r == p) {
            float2 pv = fvec[p];
            float den = pv.x*pv.x + pv.y*pv.y;
            float2 pinv = make_float2(pv.x/den, -pv.y/den);
            float2 v = RM[p][c];
            RM[p][c] = make_float2(v.x*pinv.x - v.y*pinv.y, v.x*pinv.y + v.y*pinv.x);
        }
        __syncthreads();
        if (r != p) {
            float2 f = fvec[r], pr = RM[p][c], v = RM[r][c];
            v.x -= f.x*pr.x - f.y*pr.y;
            v.y -= f.x*pr.y + f.y*pr.x;
            RM[r][c] = v;
        }
        __syncthreads();
    }
    if (t < 144) {
        int i = t / 12, j = t % 12;
        float wr = 0.f, wi = 0.f;
        #pragma unroll
        for (int k = 0; k < 12; k++) {
            float2 cm = sCm[i*12 + k], iv = RM[k][12 + j];
            wr += cm.x*iv.x - cm.y*iv.y;
            wi += cm.x*iv.y + cm.y*iv.x;
        }
        d_wm[bu*144 + t] = make_float2(wr, wi);
    }
}

// ---------------- K9: Wmmse filter + derotate + write output ----------------
__global__ void k_final(float* __restrict__ out) {
    __shared__ float2 sW[144];
    __shared__ float2 sh[192];
    int chunk = blockIdx.x % 17;
    int a  = (blockIdx.x / 17) % A;
    int bu = blockIdx.x / (17 * A);
    int b  = bu / UP;
    int t = threadIdx.x;
    int n0 = chunk * 192;
    if (t < 144) sW[t] = d_wm[bu*144 + t];
    sh[t] = hres_val(bu, a, n0 + t, b);
    __syncthreads();
    int g = t / 12, i = t % 12;
    float2 acc = {0.f, 0.f};
    #pragma unroll
    for (int j = 0; j < 12; j++) {
        float2 w = sW[i*12 + j], h = sh[g*12 + j];
        acc.x += w.x*h.x - w.y*h.y;
        acc.y += w.x*h.y + w.y*h.x;
    }
    int n = n0 + t;
    float2 ph = d_phT[bu*L + n];
    float fr = acc.x*ph.x + acc.y*ph.y;     // acc * conj(ph)
    float fi = acc.y*ph.x - acc.x*ph.y;
    int oidx = ((bu*A + a)*L + n) * 2;
    out[oidx]     = fr;
    out[oidx + 1] = fi;
}

extern "C" void kernel_launch(void* const* d_in, const int* in_sizes, int n_in,
                              void* d_out, int out_size) {
    const float* lr = (const float*)d_in[0];
    const float* li = (const float*)d_in[1];
    const int*   cs = (const int*)d_in[2];
    const float* W1 = (const float*)d_in[3];
    const float* b1 = (const float*)d_in[4];
    const float* W2 = (const float*)d_in[5];
    const float* b2 = (const float*)d_in[6];
    float* out = (float*)d_out;

    k_dft<<<dim3(KSPLIT, NAG, B), 512>>>(lr, li, cs);
    k_peak<<<dim3(UP, B), 64>>>(cs);
    k_phasor<<<(NM*L)/256, 256>>>();
    k_havg<<<(NM*A*L4)/256, 256>>>(lr, li);
    k_residual<<<(B*A*L)/256, 256>>>(lr, li);
    k_energy<<<NM*A, 256>>>();
    k_feat<<<NM, 256>>>();
    k_gemm1<<<dim3(GK1, H/64), 256>>>(W1);
    k_h1<<<NM, H>>>(b1);
    k_gemm2<<<NM, NOUT>>>(W2, b2);
    k_wmmse<<<NM, 288>>>();
    k_final<<<NM*A*17, 192>>>(out);
}